// round 15
// baseline (speedup 1.0000x reference)
#include <cuda_runtime.h>
#include <cuda_fp16.h>
#include <math.h>
#include <stdint.h>

#define Bv 4
#define Nv 2048
#define Cv 1024
#define Hv 16
#define Dv 64
#define Mv (Bv*Nv)          // 8192
#define F3 (3*Cv)           // 3072

// ---------------- scratch (static device arrays; no allocation) --------------
__device__ __half g_q[Bv*Hv*Nv*Dv];         // [B,H,N,D] fp16, exp2-pre-scaled
__device__ __half g_k[Bv*Hv*Nv*Dv];         // [B,H,N,D] fp16
__device__ __half g_vT[Bv*Hv*Dv*Nv];        // [B,H,D,N] fp16 (transposed)
__device__ __half g_att[Mv * Cv];           // [B,N,C] fp16
__device__ __half g_xh[Mv * Cv];            // x fp16
__device__ __half g_wqh[F3 * Cv];           // w_qkv fp16
__device__ __half g_wph[Cv * Cv];           // w_proj fp16

// ======================= PTX helpers (plain sm_103-legal) ====================
__device__ __forceinline__ uint32_t smem_u32(const void* p) {
    uint32_t a;
    asm("{ .reg .u64 t; cvta.to.shared.u64 t, %1; cvt.u32.u64 %0, t; }"
        : "=r"(a) : "l"(p));
    return a;
}
__device__ __forceinline__ void cpa16(uint32_t dst, const void* src) {
    asm volatile("cp.async.cg.shared.global [%0], [%1], 16;"
                 :: "r"(dst), "l"(src));
}
#define CP_COMMIT() asm volatile("cp.async.commit_group;" ::: "memory")
#define CP_WAIT(n)  asm volatile("cp.async.wait_group %0;" :: "n"(n) : "memory")

#define LDSM4(r0, r1, r2, r3, addr) \
    asm volatile("ldmatrix.sync.aligned.m8n8.x4.shared.b16 {%0,%1,%2,%3}, [%4];" \
        : "=r"(r0), "=r"(r1), "=r"(r2), "=r"(r3) : "r"(addr))

#define MMA_F16(c, a, b) \
    asm volatile("mma.sync.aligned.m16n8k16.row.col.f32.f16.f16.f32 " \
        "{%0,%1,%2,%3}, {%4,%5,%6,%7}, {%8,%9}, {%0,%1,%2,%3};" \
        : "+f"((c)[0]), "+f"((c)[1]), "+f"((c)[2]), "+f"((c)[3]) \
        : "r"((a)[0]), "r"((a)[1]), "r"((a)[2]), "r"((a)[3]), \
          "r"((b)[0]), "r"((b)[1]))

__device__ __forceinline__ float ex2(float x) {
    float r;
    asm("ex2.approx.ftz.f32 %0, %1;" : "=f"(r) : "f"(x));
    return r;
}
__device__ __forceinline__ uint32_t h2u(float a, float b) {
    __half2 h = __floats2half2_rn(a, b);
    return *(uint32_t*)&h;
}

// ---------------- merged fp32 -> fp16 conversion (3 arrays, 1 launch) --------
__global__ __launch_bounds__(256) void cvt3_f16(
    const float4* __restrict__ a, __half* __restrict__ ah, int na,
    const float4* __restrict__ b, __half* __restrict__ bh, int nb,
    const float4* __restrict__ c, __half* __restrict__ ch, int nc)
{
    int i = blockIdx.x * 256 + threadIdx.x;
    const float4* src; __half* dst; int j = i;
    if (i < na)               { src = a; dst = ah; }
    else if (i < na + nb)     { src = b; dst = bh; j = i - na; }
    else if (i < na + nb + nc){ src = c; dst = ch; j = i - na - nb; }
    else return;
    float4 v = src[j];
    *(__half2*)(dst + 4 * (size_t)j)     = __floats2half2_rn(v.x, v.y);
    *(__half2*)(dst + 4 * (size_t)j + 2) = __floats2half2_rn(v.z, v.w);
}

// ======== GEMM config: 128x128 tile, 4 warps of 64x64, 2-stage, k=64 =========
#define GPH 72                             // halves per row (64 + 8 pad)
#define GSTG (128*GPH)                     // halves per operand per stage
#define GEMM_SMEM (2 * 2 * GSTG * 2)       // 73728 B -> 2 CTAs/SM
#define PQ 131                             // fp32 staging pitch (mod 32 = 3)

// Shared mainloop body (macro-free duplication kept readable via lambdas).
// Warp grid: wm=(w>>1)*64, wn=(w&1)*64. acc[4][8][4].

// ================== fused QKV GEMM + RoPE + layout epilogue ==================
__global__ __launch_bounds__(128, 2) void gemm_qkv(
    const __half* __restrict__ A, const __half* __restrict__ Bw,
    __half* __restrict__ q, __half* __restrict__ k, __half* __restrict__ vT,
    const float* __restrict__ ct, const float* __restrict__ st)
{
    extern __shared__ char smraw[];
    const int tid = threadIdx.x, l = tid & 31, w = tid >> 5;
    const int wm = (w >> 1) * 64, wn = (w & 1) * 64;
    const int bm = blockIdx.y * 128, bn = blockIdx.x * 128;
    const int K = Cv;
    const uint32_t base_u = smem_u32(smraw);

    const __half* Ag = A  + (size_t)bm * K;
    const __half* Bg = Bw + (size_t)bn * K;

    int aoff[4], boff[4];
#pragma unroll
    for (int mi = 0; mi < 4; mi++)
        aoff[mi] = (wm + mi * 16 + (l & 15)) * GPH + ((l >> 4) & 1) * 8;
#pragma unroll
    for (int p = 0; p < 4; p++)
        boff[p] = (wn + p * 16 + ((l >> 4) << 3) + (l & 7)) * GPH + ((l >> 3) & 1) * 8;

    float acc[4][8][4];
#pragma unroll
    for (int mi = 0; mi < 4; mi++)
#pragma unroll
        for (int ni = 0; ni < 8; ni++)
#pragma unroll
            for (int e = 0; e < 4; e++) acc[mi][ni][e] = 0.f;

    const int NIT = K / 64;   // 16

    // per stage per operand: 128 rows x 8 chunks -> 1024; 2048 total / 128 thr
    auto issue = [&](int i) {
        const int k0 = i * 64;
        const uint32_t au = base_u + (uint32_t)((i & 1) * 2 * GSTG) * 2;
        const uint32_t bu = au + GSTG * 2;
#pragma unroll
        for (int j = 0; j < 8; j++) {
            int c = tid + 128 * j;
            int row = c >> 3, seg = (c & 7) * 8;
            cpa16(au + (uint32_t)(row * GPH + seg) * 2, Ag + (size_t)row * K + k0 + seg);
            cpa16(bu + (uint32_t)(row * GPH + seg) * 2, Bg + (size_t)row * K + k0 + seg);
        }
    };

    issue(0); CP_COMMIT();

    for (int i = 0; i < NIT; i++) {
        CP_WAIT(0);
        __syncthreads();                   // all warps done with compute(i-1)
        if (i + 1 < NIT) { issue(i + 1); CP_COMMIT(); }

        const uint32_t au = base_u + (uint32_t)((i & 1) * 2 * GSTG) * 2;
        const uint32_t bu = au + GSTG * 2;
#pragma unroll
        for (int ks = 0; ks < 4; ks++) {
            const int k0 = ks * 16;
            uint32_t a[4][4], b[8][2];
#pragma unroll
            for (int mi = 0; mi < 4; mi++)
                LDSM4(a[mi][0], a[mi][1], a[mi][2], a[mi][3],
                      au + (uint32_t)(aoff[mi] + k0) * 2);
#pragma unroll
            for (int p = 0; p < 4; p++)
                LDSM4(b[2*p][0], b[2*p][1], b[2*p+1][0], b[2*p+1][1],
                      bu + (uint32_t)(boff[p] + k0) * 2);
#pragma unroll
            for (int mi = 0; mi < 4; mi++)
#pragma unroll
                for (int ni = 0; ni < 8; ni++)
                    MMA_F16(acc[mi][ni], a[mi], b[ni]);
        }
    }

    // ---- stage fp32 accumulators in smem (reuses stage memory) ----
    __syncthreads();
    float* Cs = (float*)smraw;             // 128 x PQ fp32 = 67072 B (fits 73728)
    const int rr = l >> 2, cc = (l & 3) * 2;
#pragma unroll
    for (int mi = 0; mi < 4; mi++)
#pragma unroll
        for (int ni = 0; ni < 8; ni++) {
            const int row = wm + mi * 16 + rr;
            const int col = wn + ni * 8 + cc;
            Cs[row * PQ + col]     = acc[mi][ni][0];
            Cs[row * PQ + col + 1] = acc[mi][ni][1];
            Cs[(row + 8) * PQ + col]     = acc[mi][ni][2];
            Cs[(row + 8) * PQ + col + 1] = acc[mi][ni][3];
        }
    __syncthreads();

    // ---- fused epilogue: rope for q/k, transpose for v ----
    const int type  = bn >> 10;            // 0=q, 1=k, 2=v
    const int hbase = (bn & 1023) >> 6;    // first head in this tile
    const int b_ = bm >> 11;               // batch
    const int n0 = bm & 2047;              // first seq position
    const float scale = 0.125f * 1.4426950408889634f;   // D^-0.5 * log2(e)

    if (type < 2) {
        __half* dst = (type == 0) ? q : k;
        const float sc = (type == 0) ? scale : 1.0f;
#pragma unroll
        for (int it = 0; it < 64; it++) {
            int pi = tid + 128 * it;             // 128 rows x 2 heads x 32 dh
            int dh = pi & 31;
            int hh = (pi >> 5) & 1;
            int r  = pi >> 6;
            float x0 = Cs[r * PQ + hh * 64 + dh];
            float x1 = Cs[r * PQ + hh * 64 + dh + 32];
            int n = n0 + r;
            float c0 = ct[n * 64 + dh], c1 = ct[n * 64 + dh + 32];
            float s0 = st[n * 64 + dh], s1 = st[n * 64 + dh + 32];
            float y0 = (x0 * c0 - x1 * s0) * sc;
            float y1 = (x1 * c1 + x0 * s1) * sc;
            size_t obase = ((size_t)((b_ * Hv + hbase + hh) * Nv + n)) * 64 + dh;
            dst[obase]      = __float2half_rn(y0);
            dst[obase + 32] = __float2half_rn(y1);
        }
    } else {
#pragma unroll
        for (int it = 0; it < 128; it++) {
            int vi = tid + 128 * it;             // 128 d x 128 n
            int nl = vi & 127;
            int d  = vi >> 7;
            float vv = Cs[nl * PQ + d];
            size_t o = ((size_t)((b_ * Hv + hbase + (d >> 6)) * 64 + (d & 63))) * Nv
                     + n0 + nl;
            vT[o] = __float2half_rn(vv);
        }
    }
}

// ================== generic FP16 GEMM (proj): C = A * B^T + bias =============
__global__ __launch_bounds__(128, 2) void gemm_h(
    const __half* __restrict__ A, const __half* __restrict__ Bw,
    float* __restrict__ C, int Nn, int K, const float* __restrict__ bias)
{
    extern __shared__ char smraw[];
    const int tid = threadIdx.x, l = tid & 31, w = tid >> 5;
    const int wm = (w >> 1) * 64, wn = (w & 1) * 64;
    const int bm = blockIdx.y * 128, bn = blockIdx.x * 128;
    const uint32_t base_u = smem_u32(smraw);

    const __half* Ag = A  + (size_t)bm * K;
    const __half* Bg = Bw + (size_t)bn * K;

    int aoff[4], boff[4];
#pragma unroll
    for (int mi = 0; mi < 4; mi++)
        aoff[mi] = (wm + mi * 16 + (l & 15)) * GPH + ((l >> 4) & 1) * 8;
#pragma unroll
    for (int p = 0; p < 4; p++)
        boff[p] = (wn + p * 16 + ((l >> 4) << 3) + (l & 7)) * GPH + ((l >> 3) & 1) * 8;

    float acc[4][8][4];
#pragma unroll
    for (int mi = 0; mi < 4; mi++)
#pragma unroll
        for (int ni = 0; ni < 8; ni++)
#pragma unroll
            for (int e = 0; e < 4; e++) acc[mi][ni][e] = 0.f;

    const int NIT = K / 64;

    auto issue = [&](int i) {
        const int k0 = i * 64;
        const uint32_t au = base_u + (uint32_t)((i & 1) * 2 * GSTG) * 2;
        const uint32_t bu = au + GSTG * 2;
#pragma unroll
        for (int j = 0; j < 8; j++) {
            int c = tid + 128 * j;
            int row = c >> 3, seg = (c & 7) * 8;
            cpa16(au + (uint32_t)(row * GPH + seg) * 2, Ag + (size_t)row * K + k0 + seg);
            cpa16(bu + (uint32_t)(row * GPH + seg) * 2, Bg + (size_t)row * K + k0 + seg);
        }
    };

    issue(0); CP_COMMIT();

    for (int i = 0; i < NIT; i++) {
        CP_WAIT(0);
        __syncthreads();
        if (i + 1 < NIT) { issue(i + 1); CP_COMMIT(); }

        const uint32_t au = base_u + (uint32_t)((i & 1) * 2 * GSTG) * 2;
        const uint32_t bu = au + GSTG * 2;
#pragma unroll
        for (int ks = 0; ks < 4; ks++) {
            const int k0 = ks * 16;
            uint32_t a[4][4], b[8][2];
#pragma unroll
            for (int mi = 0; mi < 4; mi++)
                LDSM4(a[mi][0], a[mi][1], a[mi][2], a[mi][3],
                      au + (uint32_t)(aoff[mi] + k0) * 2);
#pragma unroll
            for (int p = 0; p < 4; p++)
                LDSM4(b[2*p][0], b[2*p][1], b[2*p+1][0], b[2*p+1][1],
                      bu + (uint32_t)(boff[p] + k0) * 2);
#pragma unroll
            for (int mi = 0; mi < 4; mi++)
#pragma unroll
                for (int ni = 0; ni < 8; ni++)
                    MMA_F16(acc[mi][ni], a[mi], b[ni]);
        }
    }

    const int rr = l >> 2, cc = (l & 3) * 2;
#pragma unroll
    for (int mi = 0; mi < 4; mi++) {
#pragma unroll
        for (int ni = 0; ni < 8; ni++) {
            const int row = bm + wm + mi * 16 + rr;
            const int col = bn + wn + ni * 8 + cc;
            float b0 = bias[col], b1 = bias[col + 1];
            *(float2*)(C + (size_t)row * Nn + col) =
                make_float2(acc[mi][ni][0] + b0, acc[mi][ni][1] + b1);
            *(float2*)(C + (size_t)(row + 8) * Nn + col) =
                make_float2(acc[mi][ni][2] + b0, acc[mi][ni][3] + b1);
        }
    }
}

// --------- Flash attention: 4 warps, 32 q-rows/warp, shared K/V frags --------
#define APH 72                             // halves pitch (64 + 8 pad)
#define ATT_SMEM (384 * APH * 2)           // 55296 B: Q 128 + K 2x64 + V 2x64

__global__ __launch_bounds__(128, 2) void attn_mma(
    const __half* __restrict__ q, const __half* __restrict__ k,
    const __half* __restrict__ vT, __half* __restrict__ out)
{
    extern __shared__ char smraw[];
    const int bh = blockIdx.y, qt = blockIdx.x;
    const __half* qb  = q  + (size_t)bh * Nv * Dv;
    const __half* kb  = k  + (size_t)bh * Nv * Dv;
    const __half* vTb = vT + (size_t)bh * Dv * Nv;
    const int tid = threadIdx.x, l = tid & 31, w = tid >> 5;
    const int wbase = w * 32;

    const uint32_t Qu = smem_u32(smraw);
    uint32_t Ku[2], Vu[2];
    Ku[0] = Qu + 128 * APH * 2;  Ku[1] = Ku[0] + 64 * APH * 2;
    Vu[0] = Ku[1] + 64 * APH * 2;  Vu[1] = Vu[0] + 64 * APH * 2;

    int qoff[2];
#pragma unroll
    for (int mi = 0; mi < 2; mi++)
        qoff[mi] = (wbase + mi * 16 + (l & 15)) * APH + ((l >> 4) & 1) * 8;
    int koff[4];
#pragma unroll
    for (int p = 0; p < 4; p++)
        koff[p] = (p * 16 + ((l >> 4) << 3) + (l & 7)) * APH + ((l >> 3) & 1) * 8;

    auto issue_kv = [&](int kt) {
        const int slot = kt & 1;
#pragma unroll
        for (int j = 0; j < 4; j++) {
            int c = tid + 128 * j;
            int row = c >> 3, seg = (c & 7) * 8;
            cpa16(Ku[slot] + (uint32_t)(row * APH + seg) * 2,
                  kb + (size_t)(kt * 64 + row) * 64 + seg);
            cpa16(Vu[slot] + (uint32_t)(row * APH + seg) * 2,
                  vTb + (size_t)row * Nv + kt * 64 + seg);
        }
    };

    {
        const __half* qp = qb + (size_t)qt * 128 * 64;
#pragma unroll
        for (int j = 0; j < 8; j++) {
            int c = tid + 128 * j;
            int row = c >> 3, seg = (c & 7) * 8;
            cpa16(Qu + (uint32_t)(row * APH + seg) * 2, qp + (size_t)row * 64 + seg);
        }
        CP_COMMIT();
        issue_kv(0); CP_COMMIT();
    }

    float o[2][8][4];
#pragma unroll
    for (int mi = 0; mi < 2; mi++)
#pragma unroll
        for (int ni = 0; ni < 8; ni++)
#pragma unroll
            for (int e = 0; e < 4; e++) o[mi][ni][e] = 0.f;
    float lsum[4] = {0.f, 0.f, 0.f, 0.f};

    uint32_t qa[2][4][4];
    CP_WAIT(1);
    __syncthreads();
#pragma unroll
    for (int mi = 0; mi < 2; mi++)
#pragma unroll
        for (int ks = 0; ks < 4; ks++)
            LDSM4(qa[mi][ks][0], qa[mi][ks][1], qa[mi][ks][2], qa[mi][ks][3],
                  Qu + (uint32_t)(qoff[mi] + ks * 16) * 2);
    __syncwarp();

    const int NT = Nv / 64;     // 32
    for (int kt = 0; kt < NT; kt++) {
        CP_WAIT(0);
        __syncthreads();
        if (kt + 1 < NT) { issue_kv(kt + 1); CP_COMMIT(); }

        const int slot = kt & 1;
        float s[2][8][4];
#pragma unroll
        for (int mi = 0; mi < 2; mi++)
#pragma unroll
            for (int ni = 0; ni < 8; ni++)
#pragma unroll
                for (int e = 0; e < 4; e++) s[mi][ni][e] = 0.f;
#pragma unroll
        for (int ks = 0; ks < 4; ks++) {
            const int k0 = ks * 16;
            uint32_t b[8][2];
#pragma unroll
            for (int p = 0; p < 4; p++)
                LDSM4(b[2*p][0], b[2*p][1], b[2*p+1][0], b[2*p+1][1],
                      Ku[slot] + (uint32_t)(koff[p] + k0) * 2);
#pragma unroll
            for (int mi = 0; mi < 2; mi++)
#pragma unroll
                for (int ni = 0; ni < 8; ni++)
                    MMA_F16(s[mi][ni], qa[mi][ks], b[ni]);
        }

#pragma unroll
        for (int mi = 0; mi < 2; mi++) {
            float rs0 = 0.f, rs1 = 0.f;
#pragma unroll
            for (int ni = 0; ni < 8; ni++) {
                s[mi][ni][0] = ex2(s[mi][ni][0]); rs0 += s[mi][ni][0];
                s[mi][ni][1] = ex2(s[mi][ni][1]); rs0 += s[mi][ni][1];
                s[mi][ni][2] = ex2(s[mi][ni][2]); rs1 += s[mi][ni][2];
                s[mi][ni][3] = ex2(s[mi][ni][3]); rs1 += s[mi][ni][3];
            }
            lsum[2*mi]   += rs0;
            lsum[2*mi+1] += rs1;
        }

#pragma unroll
        for (int ks = 0; ks < 4; ks++) {
            const int k0 = ks * 16;
            uint32_t b[8][2];
#pragma unroll
            for (int p = 0; p < 4; p++)
                LDSM4(b[2*p][0], b[2*p][1], b[2*p+1][0], b[2*p+1][1],
                      Vu[slot] + (uint32_t)(koff[p] + k0) * 2);
#pragma unroll
            for (int mi = 0; mi < 2; mi++) {
                uint32_t a[4];
                a[0] = h2u(s[mi][2*ks][0],   s[mi][2*ks][1]);
                a[1] = h2u(s[mi][2*ks][2],   s[mi][2*ks][3]);
                a[2] = h2u(s[mi][2*ks+1][0], s[mi][2*ks+1][1]);
                a[3] = h2u(s[mi][2*ks+1][2], s[mi][2*ks+1][3]);
#pragma unroll
                for (int ni = 0; ni < 8; ni++)
                    MMA_F16(o[mi][ni], a, b[ni]);
            }
        }
    }

#pragma unroll
    for (int r = 0; r < 4; r++) {
        lsum[r] += __shfl_xor_sync(0xffffffffu, lsum[r], 1);
        lsum[r] += __shfl_xor_sync(0xffffffffu, lsum[r], 2);
    }

    const int b_ = bh >> 4, h_ = bh & 15;
#pragma unroll
    for (int mi = 0; mi < 2; mi++) {
        const float i0 = 1.f / lsum[2*mi], i1 = 1.f / lsum[2*mi+1];
        const int n0 = qt * 128 + wbase + mi * 16 + (l >> 2);
#pragma unroll
        for (int ni = 0; ni < 8; ni++) {
            const int col = h_ * 64 + ni * 8 + (l & 3) * 2;
            __half2 v0 = __floats2half2_rn(o[mi][ni][0] * i0, o[mi][ni][1] * i0);
            __half2 v1 = __floats2half2_rn(o[mi][ni][2] * i1, o[mi][ni][3] * i1);
            *(__half2*)(out + (size_t)(b_ * Nv + n0) * Cv + col) = v0;
            *(__half2*)(out + (size_t)(b_ * Nv + n0 + 8) * Cv + col) = v1;
        }
    }
}

// ---------------- launch -----------------------------------------------------
extern "C" void kernel_launch(void* const* d_in, const int* in_sizes, int n_in,
                              void* d_out, int out_size)
{
    const float* x        = (const float*)d_in[0];
    const float* rope_cos = (const float*)d_in[1];
    const float* rope_sin = (const float*)d_in[2];
    const float* w_qkv    = (const float*)d_in[3];
    const float* w_proj   = (const float*)d_in[4];
    const float* b_proj   = (const float*)d_in[5];
    float* out = (float*)d_out;

    __half *qh, *kh, *vT, *att, *xh, *wqh, *wph;
    cudaGetSymbolAddress((void**)&qh,  g_q);
    cudaGetSymbolAddress((void**)&kh,  g_k);
    cudaGetSymbolAddress((void**)&vT,  g_vT);
    cudaGetSymbolAddress((void**)&att, g_att);
    cudaGetSymbolAddress((void**)&xh,  g_xh);
    cudaGetSymbolAddress((void**)&wqh, g_wqh);
    cudaGetSymbolAddress((void**)&wph, g_wph);

    cudaFuncSetAttribute(gemm_qkv, cudaFuncAttributeMaxDynamicSharedMemorySize, GEMM_SMEM);
    cudaFuncSetAttribute(gemm_h,   cudaFuncAttributeMaxDynamicSharedMemorySize, GEMM_SMEM);
    cudaFuncSetAttribute(attn_mma, cudaFuncAttributeMaxDynamicSharedMemorySize, ATT_SMEM);

    // 0) convert inputs to fp16 (one launch for all three arrays)
    const int na = Mv * Cv / 4, nb = F3 * Cv / 4, nc = Cv * Cv / 4;
    cvt3_f16<<<(na + nb + nc + 255) / 256, 256>>>(
        (const float4*)x, xh, na,
        (const float4*)w_qkv, wqh, nb,
        (const float4*)w_proj, wph, nc);

    // 1) QKV GEMM fused with RoPE + q/k/vT layout (4 warps, 64x64/warp)
    gemm_qkv<<<dim3(F3 / 128, Mv / 128), 128, GEMM_SMEM>>>(
        xh, wqh, qh, kh, vT, rope_cos, rope_sin);

    // 2) Flash attention (4 warps, 32 q-rows/warp, shared K/V fragments)
    attn_mma<<<dim3(Nv / 128, Bv * Hv), 128, ATT_SMEM>>>(qh, kh, vT, att);

    // 3) projection + bias (4 warps, 64x64/warp)
    gemm_h<<<dim3(Cv / 128, Mv / 128), 128, GEMM_SMEM>>>(att, wph, out, Cv, Cv, b_proj);
}

// round 16
// speedup vs baseline: 1.0328x; 1.0328x over previous
#include <cuda_runtime.h>
#include <cuda_fp16.h>
#include <math.h>
#include <stdint.h>

#define Bv 4
#define Nv 2048
#define Cv 1024
#define Hv 16
#define Dv 64
#define Mv (Bv*Nv)          // 8192
#define F3 (3*Cv)           // 3072
#define NPERSIST 296

// ---------------- scratch (static device arrays; no allocation) --------------
__device__ __half g_q[Bv*Hv*Nv*Dv];         // [B,H,N,D] fp16, exp2-pre-scaled
__device__ __half g_k[Bv*Hv*Nv*Dv];         // [B,H,N,D] fp16
__device__ __half g_vT[Bv*Hv*Dv*Nv];        // [B,H,D,N] fp16 (transposed)
__device__ __half g_att[Mv * Cv];           // [B,N,C] fp16
__device__ __half g_xh[Mv * Cv];            // x fp16
__device__ __half g_wqh[F3 * Cv];           // w_qkv fp16
__device__ __half g_wph[Cv * Cv];           // w_proj fp16

// ======================= PTX helpers (plain sm_103-legal) ====================
__device__ __forceinline__ uint32_t smem_u32(const void* p) {
    uint32_t a;
    asm("{ .reg .u64 t; cvta.to.shared.u64 t, %1; cvt.u32.u64 %0, t; }"
        : "=r"(a) : "l"(p));
    return a;
}
__device__ __forceinline__ void cpa16(uint32_t dst, const void* src) {
    asm volatile("cp.async.cg.shared.global [%0], [%1], 16;"
                 :: "r"(dst), "l"(src));
}
#define CP_COMMIT() asm volatile("cp.async.commit_group;" ::: "memory")
#define CP_WAIT(n)  asm volatile("cp.async.wait_group %0;" :: "n"(n) : "memory")

#define LDSM4(r0, r1, r2, r3, addr) \
    asm volatile("ldmatrix.sync.aligned.m8n8.x4.shared.b16 {%0,%1,%2,%3}, [%4];" \
        : "=r"(r0), "=r"(r1), "=r"(r2), "=r"(r3) : "r"(addr))

#define MMA_F16(c, a, b) \
    asm volatile("mma.sync.aligned.m16n8k16.row.col.f32.f16.f16.f32 " \
        "{%0,%1,%2,%3}, {%4,%5,%6,%7}, {%8,%9}, {%0,%1,%2,%3};" \
        : "+f"((c)[0]), "+f"((c)[1]), "+f"((c)[2]), "+f"((c)[3]) \
        : "r"((a)[0]), "r"((a)[1]), "r"((a)[2]), "r"((a)[3]), \
          "r"((b)[0]), "r"((b)[1]))

__device__ __forceinline__ float ex2(float x) {
    float r;
    asm("ex2.approx.ftz.f32 %0, %1;" : "=f"(r) : "f"(x));
    return r;
}
__device__ __forceinline__ uint32_t h2u(float a, float b) {
    __half2 h = __floats2half2_rn(a, b);
    return *(uint32_t*)&h;
}

// ---------------- merged fp32 -> fp16 conversion (3 arrays, 1 launch) --------
__global__ __launch_bounds__(256) void cvt3_f16(
    const float4* __restrict__ a, __half* __restrict__ ah, int na,
    const float4* __restrict__ b, __half* __restrict__ bh, int nb,
    const float4* __restrict__ c, __half* __restrict__ ch, int nc)
{
    int i = blockIdx.x * 256 + threadIdx.x;
    const float4* src; __half* dst; int j = i;
    if (i < na)               { src = a; dst = ah; }
    else if (i < na + nb)     { src = b; dst = bh; j = i - na; }
    else if (i < na + nb + nc){ src = c; dst = ch; j = i - na - nb; }
    else return;
    float4 v = src[j];
    *(__half2*)(dst + 4 * (size_t)j)     = __floats2half2_rn(v.x, v.y);
    *(__half2*)(dst + 4 * (size_t)j + 2) = __floats2half2_rn(v.z, v.w);
}

// ===== GEMM config (measured-best): 128x128 tile, 8 warps 64x32, 3-stage =====
#define GPH 72                             // halves per row (64 + 8 pad)
#define GSTG (128*GPH)                     // halves per operand per stage
#define GEMM_SMEM (3 * 2 * GSTG * 2)       // 110592 B
#define PQ 131                             // fp32 staging pitch (mod 32 = 3)

// ================== fused QKV GEMM + RoPE + layout epilogue ==================
__global__ __launch_bounds__(256, 2) void gemm_qkv(
    const __half* __restrict__ A, const __half* __restrict__ Bw,
    __half* __restrict__ q, __half* __restrict__ k, __half* __restrict__ vT,
    const float* __restrict__ ct, const float* __restrict__ st)
{
    extern __shared__ char smraw[];
    const int tid = threadIdx.x, l = tid & 31, w = tid >> 5;
    const int wm = (w & 1) * 64, wn = (w >> 1) * 32;
    const int bm = blockIdx.y * 128, bn = blockIdx.x * 128;
    const int K = Cv;
    const uint32_t base_u = smem_u32(smraw);

    const __half* Ag = A  + (size_t)bm * K;
    const __half* Bg = Bw + (size_t)bn * K;

    int aoff[4], boff[2];
#pragma unroll
    for (int mi = 0; mi < 4; mi++)
        aoff[mi] = (wm + mi * 16 + (l & 15)) * GPH + ((l >> 4) & 1) * 8;
#pragma unroll
    for (int p = 0; p < 2; p++)
        boff[p] = (wn + p * 16 + ((l >> 4) << 3) + (l & 7)) * GPH + ((l >> 3) & 1) * 8;

    float acc[4][4][4];
#pragma unroll
    for (int mi = 0; mi < 4; mi++)
#pragma unroll
        for (int ni = 0; ni < 4; ni++)
#pragma unroll
            for (int e = 0; e < 4; e++) acc[mi][ni][e] = 0.f;

    const int NIT = K / 64;   // 16

    auto issue = [&](int i) {
        const int k0 = i * 64;
        const int st_ = i % 3;
        const uint32_t au = base_u + (uint32_t)(st_ * 2 * GSTG) * 2;
        const uint32_t bu = au + GSTG * 2;
#pragma unroll
        for (int j = 0; j < 4; j++) {
            int c = tid + 256 * j;
            int row = c >> 3, seg = (c & 7) * 8;
            cpa16(au + (uint32_t)(row * GPH + seg) * 2, Ag + (size_t)row * K + k0 + seg);
            cpa16(bu + (uint32_t)(row * GPH + seg) * 2, Bg + (size_t)row * K + k0 + seg);
        }
    };

    issue(0); CP_COMMIT();
    issue(1); CP_COMMIT();

    for (int i = 0; i < NIT; i++) {
        if (i == NIT - 1) { CP_WAIT(0); } else { CP_WAIT(1); }
        __syncthreads();
        if (i + 2 < NIT) { issue(i + 2); CP_COMMIT(); }

        const int st_ = i % 3;
        const uint32_t au = base_u + (uint32_t)(st_ * 2 * GSTG) * 2;
        const uint32_t bu = au + GSTG * 2;
#pragma unroll
        for (int ks = 0; ks < 4; ks++) {
            const int k0 = ks * 16;
            uint32_t a[4][4], b[4][2];
#pragma unroll
            for (int mi = 0; mi < 4; mi++)
                LDSM4(a[mi][0], a[mi][1], a[mi][2], a[mi][3],
                      au + (uint32_t)(aoff[mi] + k0) * 2);
#pragma unroll
            for (int p = 0; p < 2; p++)
                LDSM4(b[2*p][0], b[2*p][1], b[2*p+1][0], b[2*p+1][1],
                      bu + (uint32_t)(boff[p] + k0) * 2);
#pragma unroll
            for (int mi = 0; mi < 4; mi++)
#pragma unroll
                for (int ni = 0; ni < 4; ni++)
                    MMA_F16(acc[mi][ni], a[mi], b[ni]);
        }
    }

    // ---- stage fp32 accumulators in smem (reuses stage memory) ----
    __syncthreads();
    float* Cs = (float*)smraw;             // 128 x PQ fp32
    const int rr = l >> 2, cc = (l & 3) * 2;
#pragma unroll
    for (int mi = 0; mi < 4; mi++)
#pragma unroll
        for (int ni = 0; ni < 4; ni++) {
            const int row = wm + mi * 16 + rr;
            const int col = wn + ni * 8 + cc;
            Cs[row * PQ + col]     = acc[mi][ni][0];
            Cs[row * PQ + col + 1] = acc[mi][ni][1];
            Cs[(row + 8) * PQ + col]     = acc[mi][ni][2];
            Cs[(row + 8) * PQ + col + 1] = acc[mi][ni][3];
        }
    __syncthreads();

    // ---- fused epilogue: rope for q/k, transpose for v ----
    const int type  = bn >> 10;            // 0=q, 1=k, 2=v
    const int hbase = (bn & 1023) >> 6;    // first head in this tile
    const int b_ = bm >> 11;               // batch
    const int n0 = bm & 2047;              // first seq position
    const float scale = 0.125f * 1.4426950408889634f;   // D^-0.5 * log2(e)

    if (type < 2) {
        __half* dst = (type == 0) ? q : k;
        const float sc = (type == 0) ? scale : 1.0f;
#pragma unroll
        for (int it = 0; it < 32; it++) {
            int pi = tid + 256 * it;
            int dh = pi & 31;
            int hh = (pi >> 5) & 1;
            int r  = pi >> 6;
            float x0 = Cs[r * PQ + hh * 64 + dh];
            float x1 = Cs[r * PQ + hh * 64 + dh + 32];
            int n = n0 + r;
            float c0 = ct[n * 64 + dh], c1 = ct[n * 64 + dh + 32];
            float s0 = st[n * 64 + dh], s1 = st[n * 64 + dh + 32];
            float y0 = (x0 * c0 - x1 * s0) * sc;
            float y1 = (x1 * c1 + x0 * s1) * sc;
            size_t obase = ((size_t)((b_ * Hv + hbase + hh) * Nv + n)) * 64 + dh;
            dst[obase]      = __float2half_rn(y0);
            dst[obase + 32] = __float2half_rn(y1);
        }
    } else {
#pragma unroll
        for (int it = 0; it < 64; it++) {
            int vi = tid + 256 * it;
            int nl = vi & 127;
            int d  = vi >> 7;
            float vv = Cs[nl * PQ + d];
            size_t o = ((size_t)((b_ * Hv + hbase + (d >> 6)) * 64 + (d & 63))) * Nv
                     + n0 + nl;
            vT[o] = __float2half_rn(vv);
        }
    }
}

// ================== generic FP16 GEMM (proj): C = A * B^T + bias =============
__global__ __launch_bounds__(256, 2) void gemm_h(
    const __half* __restrict__ A, const __half* __restrict__ Bw,
    float* __restrict__ C, int Nn, int K, const float* __restrict__ bias)
{
    extern __shared__ char smraw[];
    const int tid = threadIdx.x, l = tid & 31, w = tid >> 5;
    const int wm = (w & 1) * 64, wn = (w >> 1) * 32;
    const int bm = blockIdx.y * 128, bn = blockIdx.x * 128;
    const uint32_t base_u = smem_u32(smraw);

    const __half* Ag = A  + (size_t)bm * K;
    const __half* Bg = Bw + (size_t)bn * K;

    int aoff[4], boff[2];
#pragma unroll
    for (int mi = 0; mi < 4; mi++)
        aoff[mi] = (wm + mi * 16 + (l & 15)) * GPH + ((l >> 4) & 1) * 8;
#pragma unroll
    for (int p = 0; p < 2; p++)
        boff[p] = (wn + p * 16 + ((l >> 4) << 3) + (l & 7)) * GPH + ((l >> 3) & 1) * 8;

    float acc[4][4][4];
#pragma unroll
    for (int mi = 0; mi < 4; mi++)
#pragma unroll
        for (int ni = 0; ni < 4; ni++)
#pragma unroll
            for (int e = 0; e < 4; e++) acc[mi][ni][e] = 0.f;

    const int NIT = K / 64;

    auto issue = [&](int i) {
        const int k0 = i * 64;
        const int st_ = i % 3;
        const uint32_t au = base_u + (uint32_t)(st_ * 2 * GSTG) * 2;
        const uint32_t bu = au + GSTG * 2;
#pragma unroll
        for (int j = 0; j < 4; j++) {
            int c = tid + 256 * j;
            int row = c >> 3, seg = (c & 7) * 8;
            cpa16(au + (uint32_t)(row * GPH + seg) * 2, Ag + (size_t)row * K + k0 + seg);
            cpa16(bu + (uint32_t)(row * GPH + seg) * 2, Bg + (size_t)row * K + k0 + seg);
        }
    };

    issue(0); CP_COMMIT();
    issue(1); CP_COMMIT();

    for (int i = 0; i < NIT; i++) {
        if (i == NIT - 1) { CP_WAIT(0); } else { CP_WAIT(1); }
        __syncthreads();
        if (i + 2 < NIT) { issue(i + 2); CP_COMMIT(); }

        const int st_ = i % 3;
        const uint32_t au = base_u + (uint32_t)(st_ * 2 * GSTG) * 2;
        const uint32_t bu = au + GSTG * 2;
#pragma unroll
        for (int ks = 0; ks < 4; ks++) {
            const int k0 = ks * 16;
            uint32_t a[4][4], b[4][2];
#pragma unroll
            for (int mi = 0; mi < 4; mi++)
                LDSM4(a[mi][0], a[mi][1], a[mi][2], a[mi][3],
                      au + (uint32_t)(aoff[mi] + k0) * 2);
#pragma unroll
            for (int p = 0; p < 2; p++)
                LDSM4(b[2*p][0], b[2*p][1], b[2*p+1][0], b[2*p+1][1],
                      bu + (uint32_t)(boff[p] + k0) * 2);
#pragma unroll
            for (int mi = 0; mi < 4; mi++)
#pragma unroll
                for (int ni = 0; ni < 4; ni++)
                    MMA_F16(acc[mi][ni], a[mi], b[ni]);
        }
    }

    const int rr = l >> 2, cc = (l & 3) * 2;
#pragma unroll
    for (int mi = 0; mi < 4; mi++) {
#pragma unroll
        for (int ni = 0; ni < 4; ni++) {
            const int row = bm + wm + mi * 16 + rr;
            const int col = bn + wn + ni * 8 + cc;
            float b0 = bias[col], b1 = bias[col + 1];
            *(float2*)(C + (size_t)row * Nn + col) =
                make_float2(acc[mi][ni][0] + b0, acc[mi][ni][1] + b1);
            *(float2*)(C + (size_t)(row + 8) * Nn + col) =
                make_float2(acc[mi][ni][2] + b0, acc[mi][ni][3] + b1);
        }
    }
}

// ---- Flash attention: persistent, 4 warps, 32 q-rows/warp, shared K/V ------
#define APH 72                             // halves pitch (64 + 8 pad)
#define ATT_SMEM (384 * APH * 2)           // 55296 B: Q 128 + K 2x64 + V 2x64
#define ATT_WORK ((Bv * Hv) * (Nv / 128))  // 1024 work items

__global__ __launch_bounds__(128, 2) void attn_mma(
    const __half* __restrict__ q, const __half* __restrict__ k,
    const __half* __restrict__ vT, __half* __restrict__ out)
{
    extern __shared__ char smraw[];
    const int tid = threadIdx.x, l = tid & 31, w = tid >> 5;
    const int wbase = w * 32;

    const uint32_t Qu = smem_u32(smraw);
    uint32_t Ku[2], Vu[2];
    Ku[0] = Qu + 128 * APH * 2;  Ku[1] = Ku[0] + 64 * APH * 2;
    Vu[0] = Ku[1] + 64 * APH * 2;  Vu[1] = Vu[0] + 64 * APH * 2;

    int qoff[2];
#pragma unroll
    for (int mi = 0; mi < 2; mi++)
        qoff[mi] = (wbase + mi * 16 + (l & 15)) * APH + ((l >> 4) & 1) * 8;
    int koff[4];
#pragma unroll
    for (int p = 0; p < 4; p++)
        koff[p] = (p * 16 + ((l >> 4) << 3) + (l & 7)) * APH + ((l >> 3) & 1) * 8;

    for (int work = blockIdx.x; work < ATT_WORK; work += gridDim.x) {
        const int qt = work & (Nv / 128 - 1);
        const int bh = work >> 4;
        const __half* qb  = q  + (size_t)bh * Nv * Dv;
        const __half* kb  = k  + (size_t)bh * Nv * Dv;
        const __half* vTb = vT + (size_t)bh * Dv * Nv;

        __syncthreads();   // protect smem from lagging warps of previous item

        auto issue_kv = [&](int kt) {
            const int slot = kt & 1;
#pragma unroll
            for (int j = 0; j < 4; j++) {
                int c = tid + 128 * j;
                int row = c >> 3, seg = (c & 7) * 8;
                cpa16(Ku[slot] + (uint32_t)(row * APH + seg) * 2,
                      kb + (size_t)(kt * 64 + row) * 64 + seg);
                cpa16(Vu[slot] + (uint32_t)(row * APH + seg) * 2,
                      vTb + (size_t)row * Nv + kt * 64 + seg);
            }
        };

        {
            const __half* qp = qb + (size_t)qt * 128 * 64;
#pragma unroll
            for (int j = 0; j < 8; j++) {
                int c = tid + 128 * j;
                int row = c >> 3, seg = (c & 7) * 8;
                cpa16(Qu + (uint32_t)(row * APH + seg) * 2, qp + (size_t)row * 64 + seg);
            }
            CP_COMMIT();
            issue_kv(0); CP_COMMIT();
        }

        float o[2][8][4];
#pragma unroll
        for (int mi = 0; mi < 2; mi++)
#pragma unroll
            for (int ni = 0; ni < 8; ni++)
#pragma unroll
                for (int e = 0; e < 4; e++) o[mi][ni][e] = 0.f;
        float lsum[4] = {0.f, 0.f, 0.f, 0.f};

        uint32_t qa[2][4][4];
        CP_WAIT(1);
        __syncthreads();
#pragma unroll
        for (int mi = 0; mi < 2; mi++)
#pragma unroll
            for (int ks = 0; ks < 4; ks++)
                LDSM4(qa[mi][ks][0], qa[mi][ks][1], qa[mi][ks][2], qa[mi][ks][3],
                      Qu + (uint32_t)(qoff[mi] + ks * 16) * 2);
        __syncwarp();

        const int NT = Nv / 64;     // 32
        for (int kt = 0; kt < NT; kt++) {
            CP_WAIT(0);
            __syncthreads();
            if (kt + 1 < NT) { issue_kv(kt + 1); CP_COMMIT(); }

            const int slot = kt & 1;
            float s[2][8][4];
#pragma unroll
            for (int mi = 0; mi < 2; mi++)
#pragma unroll
                for (int ni = 0; ni < 8; ni++)
#pragma unroll
                    for (int e = 0; e < 4; e++) s[mi][ni][e] = 0.f;
#pragma unroll
            for (int ks = 0; ks < 4; ks++) {
                const int k0 = ks * 16;
                uint32_t b[8][2];
#pragma unroll
                for (int p = 0; p < 4; p++)
                    LDSM4(b[2*p][0], b[2*p][1], b[2*p+1][0], b[2*p+1][1],
                          Ku[slot] + (uint32_t)(koff[p] + k0) * 2);
#pragma unroll
                for (int mi = 0; mi < 2; mi++)
#pragma unroll
                    for (int ni = 0; ni < 8; ni++)
                        MMA_F16(s[mi][ni], qa[mi][ks], b[ni]);
            }

#pragma unroll
            for (int mi = 0; mi < 2; mi++) {
                float rs0 = 0.f, rs1 = 0.f;
#pragma unroll
                for (int ni = 0; ni < 8; ni++) {
                    s[mi][ni][0] = ex2(s[mi][ni][0]); rs0 += s[mi][ni][0];
                    s[mi][ni][1] = ex2(s[mi][ni][1]); rs0 += s[mi][ni][1];
                    s[mi][ni][2] = ex2(s[mi][ni][2]); rs1 += s[mi][ni][2];
                    s[mi][ni][3] = ex2(s[mi][ni][3]); rs1 += s[mi][ni][3];
                }
                lsum[2*mi]   += rs0;
                lsum[2*mi+1] += rs1;
            }

#pragma unroll
            for (int ks = 0; ks < 4; ks++) {
                const int k0 = ks * 16;
                uint32_t b[8][2];
#pragma unroll
                for (int p = 0; p < 4; p++)
                    LDSM4(b[2*p][0], b[2*p][1], b[2*p+1][0], b[2*p+1][1],
                          Vu[slot] + (uint32_t)(koff[p] + k0) * 2);
#pragma unroll
                for (int mi = 0; mi < 2; mi++) {
                    uint32_t a[4];
                    a[0] = h2u(s[mi][2*ks][0],   s[mi][2*ks][1]);
                    a[1] = h2u(s[mi][2*ks][2],   s[mi][2*ks][3]);
                    a[2] = h2u(s[mi][2*ks+1][0], s[mi][2*ks+1][1]);
                    a[3] = h2u(s[mi][2*ks+1][2], s[mi][2*ks+1][3]);
#pragma unroll
                    for (int ni = 0; ni < 8; ni++)
                        MMA_F16(o[mi][ni], a, b[ni]);
                }
            }
        }

#pragma unroll
        for (int r = 0; r < 4; r++) {
            lsum[r] += __shfl_xor_sync(0xffffffffu, lsum[r], 1);
            lsum[r] += __shfl_xor_sync(0xffffffffu, lsum[r], 2);
        }

        const int b_ = bh >> 4, h_ = bh & 15;
#pragma unroll
        for (int mi = 0; mi < 2; mi++) {
            const float i0 = 1.f / lsum[2*mi], i1 = 1.f / lsum[2*mi+1];
            const int n0 = qt * 128 + wbase + mi * 16 + (l >> 2);
#pragma unroll
            for (int ni = 0; ni < 8; ni++) {
                const int col = h_ * 64 + ni * 8 + (l & 3) * 2;
                __half2 v0 = __floats2half2_rn(o[mi][ni][0] * i0, o[mi][ni][1] * i0);
                __half2 v1 = __floats2half2_rn(o[mi][ni][2] * i1, o[mi][ni][3] * i1);
                *(__half2*)(out + (size_t)(b_ * Nv + n0) * Cv + col) = v0;
                *(__half2*)(out + (size_t)(b_ * Nv + n0 + 8) * Cv + col) = v1;
            }
        }
    }
}

// ---------------- launch -----------------------------------------------------
extern "C" void kernel_launch(void* const* d_in, const int* in_sizes, int n_in,
                              void* d_out, int out_size)
{
    const float* x        = (const float*)d_in[0];
    const float* rope_cos = (const float*)d_in[1];
    const float* rope_sin = (const float*)d_in[2];
    const float* w_qkv    = (const float*)d_in[3];
    const float* w_proj   = (const float*)d_in[4];
    const float* b_proj   = (const float*)d_in[5];
    float* out = (float*)d_out;

    __half *qh, *kh, *vT, *att, *xh, *wqh, *wph;
    cudaGetSymbolAddress((void**)&qh,  g_q);
    cudaGetSymbolAddress((void**)&kh,  g_k);
    cudaGetSymbolAddress((void**)&vT,  g_vT);
    cudaGetSymbolAddress((void**)&att, g_att);
    cudaGetSymbolAddress((void**)&xh,  g_xh);
    cudaGetSymbolAddress((void**)&wqh, g_wqh);
    cudaGetSymbolAddress((void**)&wph, g_wph);

    cudaFuncSetAttribute(gemm_qkv, cudaFuncAttributeMaxDynamicSharedMemorySize, GEMM_SMEM);
    cudaFuncSetAttribute(gemm_h,   cudaFuncAttributeMaxDynamicSharedMemorySize, GEMM_SMEM);
    cudaFuncSetAttribute(attn_mma, cudaFuncAttributeMaxDynamicSharedMemorySize, ATT_SMEM);

    // 0) convert inputs to fp16 (one launch for all three arrays)
    const int na = Mv * Cv / 4, nb = F3 * Cv / 4, nc = Cv * Cv / 4;
    cvt3_f16<<<(na + nb + nc + 255) / 256, 256>>>(
        (const float4*)x, xh, na,
        (const float4*)w_qkv, wqh, nb,
        (const float4*)w_proj, wph, nc);

    // 1) QKV GEMM fused with RoPE + q/k/vT layout (8 warps, measured-best)
    gemm_qkv<<<dim3(F3 / 128, Mv / 128), 256, GEMM_SMEM>>>(
        xh, wqh, qh, kh, vT, rope_cos, rope_sin);

    // 2) Flash attention (persistent 296 CTAs, 4 warps, 32 q-rows/warp)
    attn_mma<<<NPERSIST, 128, ATT_SMEM>>>(qh, kh, vT, att);

    // 3) projection + bias (8 warps, measured-best)
    gemm_h<<<dim3(Cv / 128, Mv / 128), 256, GEMM_SMEM>>>(att, wph, out, Cv, Cv, b_proj);
}